// round 1
// baseline (speedup 1.0000x reference)
#include <cuda_runtime.h>
#include <math.h>

#define NB 16
#define CELLS 4096
#define SPB 1024
#define NC 513                 // rfft coeffs
#define STRIDE 1032            // padded floats per cell row (1026 used), 16B aligned
#define MIC_CELL 2184          // 8*256 + 8*16 + 8

// ---------------- scratch (static device arrays; zero-initialized at load) --
__device__ float g_S[(size_t)CELLS * STRIDE];     // state spectrum (interleaved re,im)
__device__ float g_V[(size_t)CELLS * STRIDE];     // pre-box spectrum
__device__ float g_micF[NB][2 * NC];              // mic-cell spectra per block
__device__ float2 g_tw[256];                      // e^{-2pi i q/512}
__device__ float2 g_wu[NC];                       // e^{-2pi i k/1024}

// ---------------- twiddle init (runs every launch; deterministic) -----------
__global__ void init_tw_kernel() {
    int t = threadIdx.x;
    if (t < 256) {
        double a = -2.0 * M_PI * (double)t / 512.0;
        g_tw[t] = make_float2((float)cos(a), (float)sin(a));
    }
    if (t < NC) {
        double a = -2.0 * M_PI * (double)t / 1024.0;
        g_wu[t] = make_float2((float)cos(a), (float)sin(a));
    }
}

// ---------------- 512-pt complex FFT, Stockham DIF, 256 threads -------------
// Input in a (natural order). Returns pointer to buffer holding natural-order
// output. One __syncthreads at entry (caller just filled a) and one per stage.
__device__ __forceinline__ float2* fft512(float2* a, float2* b, int tid) {
    __syncthreads();
    float2* src = a;
    float2* dst = b;
#pragma unroll
    for (int s = 0; s < 9; s++) {
        int m  = 1 << s;
        int jm = tid & ~(m - 1);          // j*m  (twiddle index q = j*m)
        float2 x0 = src[tid];
        float2 x1 = src[tid + 256];
        float2 w  = g_tw[jm];
        float sx = x0.x + x1.x, sy = x0.y + x1.y;
        float dx = x0.x - x1.x, dy = x0.y - x1.y;
        float wx = w.x * dx - w.y * dy;
        float wy = w.x * dy + w.y * dx;
        dst[tid + jm]     = make_float2(sx, sy);  // k + 2jm = tid + jm
        dst[tid + jm + m] = make_float2(wx, wy);
        __syncthreads();
        float2* t = src; src = dst; dst = t;
    }
    return src;   // after 9 swaps, result lives where src points
}

__device__ __forceinline__ float interp_env(const float* simp, int t) {
    // torch linear interp, align_corners=False, 16 -> 1024
    float c = ((float)t + 0.5f) * 0.015625f - 0.5f;
    c = fminf(fmaxf(c, 0.0f), 15.0f);
    float lof = floorf(c);
    int lo = (int)lof;
    int hi = min(lo + 1, 15);
    float w = c - lof;
    float v = simp[lo] * (1.0f - w) + simp[hi] * w;
    return fminf(fmaxf(v, 0.0f), 1.0f);   // clip BEFORE noise multiply
}

// ---------------- K1: env -> rfft -> V = clip(tf)*(S + E) -------------------
__global__ void __launch_bounds__(256) step_kernel(
    const float* __restrict__ tf,
    const float* __restrict__ imp,
    const float* __restrict__ noise,
    int b)
{
    __shared__ float2 bufA[512];
    __shared__ float2 bufB[512];
    __shared__ float  simp[16];

    int cell = blockIdx.x;
    int tid  = threadIdx.x;
    size_t rowBC = (size_t)b * CELLS + cell;

    const float*  irow = imp + rowBC * 16;
    const float2* nrow = (const float2*)(noise + rowBC * SPB);

    if (tid < 16) simp[tid] = irow[tid];
    __syncthreads();

    // pack env into complex-512: z[n] = env(2n) + i*env(2n+1)
#pragma unroll
    for (int n = tid; n < 512; n += 256) {
        float2 nn = nrow[n];
        float e0 = interp_env(simp, 2 * n)     * nn.x;
        float e1 = interp_env(simp, 2 * n + 1) * nn.y;
        bufA[n] = make_float2(e0, e1);
    }

    float2* Z = fft512(bufA, bufB, tid);

    const float* trow = tf + rowBC * (size_t)NC;
    float* Srow = g_S + (size_t)cell * STRIDE;
    float* Vrow = g_V + (size_t)cell * STRIDE;

    // unpack real-FFT bins, combine with state, apply filter
    for (int k = tid; k <= 512; k += 256) {
        float2 Zk = Z[k & 511];
        float2 Zm = Z[(512 - k) & 511];
        float Ax = 0.5f * (Zk.x + Zm.x);
        float Ay = 0.5f * (Zk.y - Zm.y);
        float Bx = 0.5f * (Zk.x - Zm.x);
        float By = 0.5f * (Zk.y + Zm.y);
        float2 W = g_wu[k];
        float wbx = W.x * Bx - W.y * By;
        float wby = W.x * By + W.y * Bx;
        float Ex = Ax + wby;         // X = A - i*(W*B)
        float Ey = Ay - wbx;
        float r = fminf(fmaxf(trow[k], 0.0f), 1.0f);
        float vx = r * (Srow[2 * k]     + Ex);
        float vy = r * (Srow[2 * k + 1] + Ey);
        Vrow[2 * k]     = vx;
        Vrow[2 * k + 1] = vy;
        if (cell == MIC_CELL) {
            g_micF[b][2 * k]     = vx;
            g_micF[b][2 * k + 1] = vy;
        }
    }
}

// ---------------- K2: separable 3x3x3 box sum (zero padded) -----------------
// Each block owns the FULL 16x16x16 field for an 8-float frequency chunk.
// smem layout: T[c*8 + e], c = x*256 + y*16 + z.
__global__ void __launch_bounds__(512) box_kernel() {
    extern __shared__ float T[];   // 4096*8 floats = 128KB
    int base = blockIdx.x * 8;     // chunk offset into row (0..1024 step 8)
    int tid  = threadIdx.x;

    for (int i = tid; i < CELLS * 8; i += 512) {
        int c = i >> 3, e = i & 7;
        T[i] = g_V[(size_t)c * STRIDE + base + e];
    }
    __syncthreads();

    // X pass: lines over x, stride 2048; line id l = (y*16+z)*8+e
    for (int l = tid; l < 2048; l += 512) {
        int off = l;
        float v[16];
#pragma unroll
        for (int x = 0; x < 16; x++) v[x] = T[off + x * 2048];
#pragma unroll
        for (int x = 0; x < 16; x++) {
            float s = v[x];
            if (x > 0)  s += v[x - 1];
            if (x < 15) s += v[x + 1];
            T[off + x * 2048] = s;
        }
    }
    __syncthreads();

    // Y pass: lines over y, stride 128; l = (x*16+z)*8+e
    for (int l = tid; l < 2048; l += 512) {
        int x  = l >> 7;
        int ze = l & 127;
        int off = x * 2048 + ze;
        float v[16];
#pragma unroll
        for (int y = 0; y < 16; y++) v[y] = T[off + y * 128];
#pragma unroll
        for (int y = 0; y < 16; y++) {
            float s = v[y];
            if (y > 0)  s += v[y - 1];
            if (y < 15) s += v[y + 1];
            T[off + y * 128] = s;
        }
    }
    __syncthreads();

    // Z pass: lines over z, stride 8; l = (x*16+y)*8+e
    for (int l = tid; l < 2048; l += 512) {
        int xy = l >> 3;
        int off = xy * 128 + (l & 7);
        float v[16];
#pragma unroll
        for (int z = 0; z < 16; z++) v[z] = T[off + z * 8];
#pragma unroll
        for (int z = 0; z < 16; z++) {
            float s = v[z];
            if (z > 0)  s += v[z - 1];
            if (z < 15) s += v[z + 1];
            T[off + z * 8] = s;
        }
    }
    __syncthreads();

    for (int i = tid; i < CELLS * 8; i += 512) {
        int c = i >> 3, e = i & 7;
        g_S[(size_t)c * STRIDE + base + e] = T[i];
    }
}

// ---------------- K3: 16 inverse real-FFTs for the mic rows -----------------
__global__ void __launch_bounds__(256) mic_kernel(float* __restrict__ out) {
    __shared__ float2 bufA[512];
    __shared__ float2 bufB[512];
    int b   = blockIdx.x;
    int tid = threadIdx.x;
    const float* M = g_micF[b];

    // rebuild packed spectrum Z[k] = A + B, store conj for inverse-via-forward
    for (int k = tid; k < 512; k += 256) {
        float2 Xk = make_float2(M[2 * k], M[2 * k + 1]);
        int mk = 512 - k;
        float2 Xm = make_float2(M[2 * mk], M[2 * mk + 1]);
        float Ax = 0.5f * (Xk.x + Xm.x);
        float Ay = 0.5f * (Xk.y - Xm.y);
        float Dx = 0.5f * (Xk.x - Xm.x);
        float Dy = 0.5f * (Xk.y + Xm.y);
        float2 W = g_wu[k];
        // B = i * conj(W) * D
        float cx = W.x * Dx + W.y * Dy;
        float cy = W.x * Dy - W.y * Dx;
        float Zx = Ax - cy;
        float Zy = Ay + cx;
        bufA[k] = make_float2(Zx, -Zy);
    }

    float2* Zr = fft512(bufA, bufB, tid);

    const float s = 1.0f / 512.0f;   // ortho*ortho == unnorm fwd + (1/N) inv; 1/512 on the packed ifft
    for (int n = tid; n < 512; n += 256) {
        float2 z = Zr[n];
        out[b * 1024 + 2 * n]     =  z.x * s;
        out[b * 1024 + 2 * n + 1] = -z.y * s;
    }
}

// ---------------- launch ----------------------------------------------------
extern "C" void kernel_launch(void* const* d_in, const int* in_sizes, int n_in,
                              void* d_out, int out_size) {
    const float* tf = nullptr;
    const float* imp = nullptr;
    const float* noise = nullptr;
    for (int i = 0; i < n_in; i++) {
        if      (in_sizes[i] == 33619968) tf    = (const float*)d_in[i];
        else if (in_sizes[i] == 1048576)  imp   = (const float*)d_in[i];
        else if (in_sizes[i] == 67108864) noise = (const float*)d_in[i];
    }

    void* sptr = nullptr;
    cudaGetSymbolAddress(&sptr, g_S);
    cudaMemsetAsync(sptr, 0, sizeof(float) * (size_t)CELLS * STRIDE);

    init_tw_kernel<<<1, 544>>>();

    cudaFuncSetAttribute(box_kernel, cudaFuncAttributeMaxDynamicSharedMemorySize,
                         CELLS * 8 * (int)sizeof(float));

    for (int b = 0; b < NB; b++) {
        step_kernel<<<CELLS, 256>>>(tf, imp, noise, b);
        box_kernel<<<STRIDE / 8, 512, CELLS * 8 * sizeof(float)>>>();
    }

    mic_kernel<<<NB, 256>>>((float*)d_out);
}